// round 1
// baseline (speedup 1.0000x reference)
#include <cuda_runtime.h>
#include <cuda_bf16.h>

#define CCH   256
#define HH    360
#define WW    360
#define NPTS  1024
#define CPB   8      // centers per block in projection kernel

// Scratch: a[g][k] = (relu-MLP(feature[center g])) @ w3, g in [0, 2048), k in [0, 32)
__device__ float g_a[2 * NPTS * 32];

// ---------------------------------------------------------------------------
// Kernel 1: gather + 256->256->128 MLP (relu) + @w3 projection to 32 dims.
// One block handles CPB=8 centers with 256 threads.
// ---------------------------------------------------------------------------
__global__ __launch_bounds__(256) void project_kernel(
    const float* __restrict__ feature,
    const int*   __restrict__ idx1,
    const int*   __restrict__ idx2,
    const float* __restrict__ w1, const float* __restrict__ b1,
    const float* __restrict__ w2, const float* __restrict__ b2,
    const float* __restrict__ w3)
{
    __shared__ float xs[CPB * 256];   // gathered features
    __shared__ float h1[CPB * 256];   // layer1 out
    __shared__ float h2[CPB * 128];   // layer2 out
    __shared__ float w3s[128 * 32];   // cached w3

    const int tid = threadIdx.x;
    const int g0  = blockIdx.x * CPB;

    // cache w3 (16 KB) in shared
    for (int i = tid; i < 128 * 32; i += 256) w3s[i] = w3[i];

    // gather: thread tid loads channel tid for each of the 8 centers
    #pragma unroll
    for (int t = 0; t < CPB; t++) {
        int g = g0 + t;
        const int* idx = (g < NPTS) ? idx1 : idx2;
        int i = (g < NPTS) ? g : (g - NPTS);
        int b  = idx[i];
        int hh = idx[NPTS + i];
        int ww = idx[2 * NPTS + i];
        long off = (((long)b * CCH + tid) * HH + hh) * (long)WW + ww;
        xs[t * 256 + tid] = feature[off];
    }
    __syncthreads();

    // layer 1: h1 = relu(x @ w1 + b1); thread tid owns output column tid
    {
        float acc[CPB];
        float bias = b1[tid];
        #pragma unroll
        for (int t = 0; t < CPB; t++) acc[t] = bias;
        #pragma unroll 4
        for (int c = 0; c < 256; c++) {
            float w = w1[c * 256 + tid];
            #pragma unroll
            for (int t = 0; t < CPB; t++)
                acc[t] = fmaf(xs[t * 256 + c], w, acc[t]);
        }
        #pragma unroll
        for (int t = 0; t < CPB; t++) h1[t * 256 + tid] = fmaxf(acc[t], 0.0f);
    }
    __syncthreads();

    // layer 2: h2 = relu(h1 @ w2 + b2); 128 output columns, so split the
    // 256 threads into two halves, each half handling 4 centers.
    {
        int j  = tid & 127;
        int tb = (tid >> 7) * 4;   // 0 or 4
        float acc[4];
        float bias = b2[j];
        #pragma unroll
        for (int t = 0; t < 4; t++) acc[t] = bias;
        #pragma unroll 4
        for (int c = 0; c < 256; c++) {
            float w = w2[c * 128 + j];
            #pragma unroll
            for (int t = 0; t < 4; t++)
                acc[t] = fmaf(h1[(tb + t) * 256 + c], w, acc[t]);
        }
        #pragma unroll
        for (int t = 0; t < 4; t++) h2[(tb + t) * 128 + j] = fmaxf(acc[t], 0.0f);
    }
    __syncthreads();

    // layer 3 (projection, no bias/relu): a = h2 @ w3
    // 8 groups of 32 threads; group t handles center t, lane k handles output k.
    {
        int k = tid & 31;
        int t = tid >> 5;
        float acc = 0.0f;
        #pragma unroll 4
        for (int d = 0; d < 128; d++)
            acc = fmaf(h2[t * 128 + d], w3s[d * 32 + k], acc);
        g_a[(g0 + t) * 32 + k] = acc;
    }
}

// ---------------------------------------------------------------------------
// Kernel 2: out[m,n] = b4 + sum_k relu(a1[m,k] - a2[n,k] + b3[k]) * w4[k]
// Block: 256 threads, each thread owns one n; tile of 32 m per block.
// grid = (1024/256, 1024/32) = (4, 32)
// ---------------------------------------------------------------------------
__global__ __launch_bounds__(256) void pair_kernel(
    const float* __restrict__ b3,
    const float* __restrict__ w4,
    const float* __restrict__ b4,
    float*       __restrict__ out)
{
    __shared__ float a1s[32 * 32];

    const int tid = threadIdx.x;
    const int n   = blockIdx.x * 256 + tid;
    const int m0  = blockIdx.y * 32;

    // a2p[k] = b3[k] - a2[n][k]  (so inner op is a1 + a2p), w4 in registers
    float a2p[32], w4r[32];
    const float* a2row = g_a + (NPTS + n) * 32;
    #pragma unroll
    for (int v = 0; v < 8; v++) {
        float4 f = reinterpret_cast<const float4*>(a2row)[v];
        float4 bb = reinterpret_cast<const float4*>(b3)[v];
        a2p[4*v + 0] = bb.x - f.x;
        a2p[4*v + 1] = bb.y - f.y;
        a2p[4*v + 2] = bb.z - f.z;
        a2p[4*v + 3] = bb.w - f.w;
        float4 wv = reinterpret_cast<const float4*>(w4)[v];
        w4r[4*v + 0] = wv.x; w4r[4*v + 1] = wv.y;
        w4r[4*v + 2] = wv.z; w4r[4*v + 3] = wv.w;
    }

    // stage a1 tile (32 rows x 32 cols) into shared — contiguous copy
    for (int i = tid; i < 32 * 32; i += 256)
        a1s[i] = g_a[m0 * 32 + i];
    __syncthreads();

    const float bias4 = b4[0];

    #pragma unroll 4
    for (int m = 0; m < 32; m++) {
        // dual accumulators to shorten the FFMA dependency chain
        float acc0 = bias4, acc1 = 0.0f;
        #pragma unroll
        for (int k = 0; k < 32; k += 2) {
            float v0 = fmaxf(a1s[m * 32 + k]     + a2p[k],     0.0f);
            float v1 = fmaxf(a1s[m * 32 + k + 1] + a2p[k + 1], 0.0f);
            acc0 = fmaf(v0, w4r[k],     acc0);
            acc1 = fmaf(v1, w4r[k + 1], acc1);
        }
        out[(long)(m0 + m) * 1024 + n] = acc0 + acc1;
    }
}

// ---------------------------------------------------------------------------
extern "C" void kernel_launch(void* const* d_in, const int* in_sizes, int n_in,
                              void* d_out, int out_size)
{
    const float* feature = (const float*)d_in[0];
    const int*   idx1    = (const int*)  d_in[1];
    const int*   idx2    = (const int*)  d_in[2];
    const float* w1      = (const float*)d_in[3];
    const float* b1      = (const float*)d_in[4];
    const float* w2      = (const float*)d_in[5];
    const float* b2      = (const float*)d_in[6];
    const float* w3      = (const float*)d_in[7];
    const float* b3      = (const float*)d_in[8];
    const float* w4      = (const float*)d_in[9];
    const float* b4      = (const float*)d_in[10];
    float* out = (float*)d_out;

    project_kernel<<<(2 * NPTS) / CPB, 256>>>(feature, idx1, idx2,
                                              w1, b1, w2, b2, w3);
    dim3 grid2(NPTS / 256, NPTS / 32);
    pair_kernel<<<grid2, 256>>>(b3, w4, b4, out);
}

// round 2
// speedup vs baseline: 1.1607x; 1.1607x over previous
#include <cuda_runtime.h>
#include <cuda_bf16.h>

#define CCH   256
#define HH    360
#define WW    360
#define NPTS  1024
#define CPB   8      // centers per block in projection kernel

// Scratch: a[g][k] = (relu-MLP(feature[center g])) @ w3, g in [0, 2048), k in [0, 32)
__device__ float g_a[2 * NPTS * 32];

// ---------------------------------------------------------------------------
// Kernel 1: gather + 256->256->128 MLP (relu) + @w3 projection to 32 dims.
// One block handles CPB=8 centers with 256 threads.
// ---------------------------------------------------------------------------
__global__ __launch_bounds__(256) void project_kernel(
    const float* __restrict__ feature,
    const int*   __restrict__ idx1,
    const int*   __restrict__ idx2,
    const float* __restrict__ w1, const float* __restrict__ b1,
    const float* __restrict__ w2, const float* __restrict__ b2,
    const float* __restrict__ w3)
{
    __shared__ float xs[CPB * 256];   // gathered features
    __shared__ float h1[CPB * 256];   // layer1 out
    __shared__ float h2[CPB * 128];   // layer2 out
    __shared__ float w3s[128 * 32];   // cached w3

    const int tid = threadIdx.x;
    const int g0  = blockIdx.x * CPB;

    // cache w3 (16 KB) in shared, vectorized
    {
        const float4* src = reinterpret_cast<const float4*>(w3);
        float4* dst = reinterpret_cast<float4*>(w3s);
        for (int i = tid; i < 128 * 32 / 4; i += 256) dst[i] = src[i];
    }

    // gather: thread tid loads channel tid for each of the 8 centers
    #pragma unroll
    for (int t = 0; t < CPB; t++) {
        int g = g0 + t;
        const int* idx = (g < NPTS) ? idx1 : idx2;
        int i = (g < NPTS) ? g : (g - NPTS);
        int b  = idx[i];
        int hh = idx[NPTS + i];
        int ww = idx[2 * NPTS + i];
        long off = (((long)b * CCH + tid) * HH + hh) * (long)WW + ww;
        xs[t * 256 + tid] = feature[off];
    }
    __syncthreads();

    // layer 1: h1 = relu(x @ w1 + b1); thread tid owns output column tid.
    // k unrolled by 4: activations via LDS.128 broadcast, 4 batched weight LDGs.
    {
        float acc[CPB];
        float bias = b1[tid];
        #pragma unroll
        for (int t = 0; t < CPB; t++) acc[t] = bias;

        for (int c = 0; c < 256; c += 4) {
            float wv0 = w1[(c + 0) * 256 + tid];
            float wv1 = w1[(c + 1) * 256 + tid];
            float wv2 = w1[(c + 2) * 256 + tid];
            float wv3 = w1[(c + 3) * 256 + tid];
            #pragma unroll
            for (int t = 0; t < CPB; t++) {
                float4 x = *reinterpret_cast<const float4*>(&xs[t * 256 + c]);
                acc[t] = fmaf(x.x, wv0, acc[t]);
                acc[t] = fmaf(x.y, wv1, acc[t]);
                acc[t] = fmaf(x.z, wv2, acc[t]);
                acc[t] = fmaf(x.w, wv3, acc[t]);
            }
        }
        #pragma unroll
        for (int t = 0; t < CPB; t++) h1[t * 256 + tid] = fmaxf(acc[t], 0.0f);
    }
    __syncthreads();

    // layer 2: h2 = relu(h1 @ w2 + b2); 128 output columns, two half-blocks,
    // each half handling 4 centers. Same k-by-4 vectorization.
    {
        int j  = tid & 127;
        int tb = (tid >> 7) * 4;   // 0 or 4
        float acc[4];
        float bias = b2[j];
        #pragma unroll
        for (int t = 0; t < 4; t++) acc[t] = bias;

        for (int c = 0; c < 256; c += 4) {
            float wv0 = w2[(c + 0) * 128 + j];
            float wv1 = w2[(c + 1) * 128 + j];
            float wv2 = w2[(c + 2) * 128 + j];
            float wv3 = w2[(c + 3) * 128 + j];
            #pragma unroll
            for (int t = 0; t < 4; t++) {
                float4 x = *reinterpret_cast<const float4*>(&h1[(tb + t) * 256 + c]);
                acc[t] = fmaf(x.x, wv0, acc[t]);
                acc[t] = fmaf(x.y, wv1, acc[t]);
                acc[t] = fmaf(x.z, wv2, acc[t]);
                acc[t] = fmaf(x.w, wv3, acc[t]);
            }
        }
        #pragma unroll
        for (int t = 0; t < 4; t++) h2[(tb + t) * 128 + j] = fmaxf(acc[t], 0.0f);
    }
    __syncthreads();

    // layer 3 (projection, no bias/relu): a = h2 @ w3
    // 8 groups of 32 threads; group t handles center t, lane k handles output k.
    {
        int k = tid & 31;
        int t = tid >> 5;
        float acc0 = 0.0f, acc1 = 0.0f;
        #pragma unroll 8
        for (int d = 0; d < 128; d += 2) {
            acc0 = fmaf(h2[t * 128 + d],     w3s[d * 32 + k],       acc0);
            acc1 = fmaf(h2[t * 128 + d + 1], w3s[(d + 1) * 32 + k], acc1);
        }
        g_a[(g0 + t) * 32 + k] = acc0 + acc1;
    }
}

// ---------------------------------------------------------------------------
// Kernel 2: out[m,n] = b4 + sum_k relu(a1[m,k] - a2[n,k] + b3[k]) * w4[k]
// Block: 256 threads, each thread owns one n; tile of 16 m per block.
// grid = (1024/256, 1024/16) = (4, 64) = 256 CTAs.
// ---------------------------------------------------------------------------
__global__ __launch_bounds__(256) void pair_kernel(
    const float* __restrict__ b3,
    const float* __restrict__ w4,
    const float* __restrict__ b4,
    float*       __restrict__ out)
{
    __shared__ float a1s[16 * 32];

    const int tid = threadIdx.x;
    const int n   = blockIdx.x * 256 + tid;
    const int m0  = blockIdx.y * 16;

    // a2p[k] = b3[k] - a2[n][k]  (so inner op is a1 + a2p), w4 in registers
    float a2p[32], w4r[32];
    const float* a2row = g_a + (NPTS + n) * 32;
    #pragma unroll
    for (int v = 0; v < 8; v++) {
        float4 f = reinterpret_cast<const float4*>(a2row)[v];
        float4 bb = reinterpret_cast<const float4*>(b3)[v];
        a2p[4*v + 0] = bb.x - f.x;
        a2p[4*v + 1] = bb.y - f.y;
        a2p[4*v + 2] = bb.z - f.z;
        a2p[4*v + 3] = bb.w - f.w;
        float4 wv = reinterpret_cast<const float4*>(w4)[v];
        w4r[4*v + 0] = wv.x; w4r[4*v + 1] = wv.y;
        w4r[4*v + 2] = wv.z; w4r[4*v + 3] = wv.w;
    }

    // stage a1 tile (16 rows x 32 cols = 512 floats) into shared via float4
    if (tid < 128) {
        reinterpret_cast<float4*>(a1s)[tid] =
            reinterpret_cast<const float4*>(g_a + m0 * 32)[tid];
    }
    __syncthreads();

    const float bias4 = b4[0];

    #pragma unroll 4
    for (int m = 0; m < 16; m++) {
        // dual accumulators to shorten the FFMA dependency chain
        float acc0 = bias4, acc1 = 0.0f;
        #pragma unroll
        for (int v = 0; v < 8; v++) {
            float4 a = *reinterpret_cast<const float4*>(&a1s[m * 32 + v * 4]);
            float t0 = fmaxf(a.x + a2p[4*v + 0], 0.0f);
            float t1 = fmaxf(a.y + a2p[4*v + 1], 0.0f);
            float t2 = fmaxf(a.z + a2p[4*v + 2], 0.0f);
            float t3 = fmaxf(a.w + a2p[4*v + 3], 0.0f);
            acc0 = fmaf(t0, w4r[4*v + 0], acc0);
            acc1 = fmaf(t1, w4r[4*v + 1], acc1);
            acc0 = fmaf(t2, w4r[4*v + 2], acc0);
            acc1 = fmaf(t3, w4r[4*v + 3], acc1);
        }
        out[(long)(m0 + m) * 1024 + n] = acc0 + acc1;
    }
}

// ---------------------------------------------------------------------------
extern "C" void kernel_launch(void* const* d_in, const int* in_sizes, int n_in,
                              void* d_out, int out_size)
{
    const float* feature = (const float*)d_in[0];
    const int*   idx1    = (const int*)  d_in[1];
    const int*   idx2    = (const int*)  d_in[2];
    const float* w1      = (const float*)d_in[3];
    const float* b1      = (const float*)d_in[4];
    const float* w2      = (const float*)d_in[5];
    const float* b2      = (const float*)d_in[6];
    const float* w3      = (const float*)d_in[7];
    const float* b3      = (const float*)d_in[8];
    const float* w4      = (const float*)d_in[9];
    const float* b4      = (const float*)d_in[10];
    float* out = (float*)d_out;

    project_kernel<<<(2 * NPTS) / CPB, 256>>>(feature, idx1, idx2,
                                              w1, b1, w2, b2, w3);
    dim3 grid2(NPTS / 256, NPTS / 16);
    pair_kernel<<<grid2, 256>>>(b3, w4, b4, out);
}